// round 5
// baseline (speedup 1.0000x reference)
#include <cuda_runtime.h>
#include <cuda_bf16.h>
#include <mma.h>

using namespace nvcuda;

// Problem constants
#define BATCH 32
#define CIN   256
#define COUT  256
#define NEXP  8
#define CHID  64
#define HW    3136   // 56*56

// GEMM tiling: BM = full COUT so each x element is loaded by exactly one CTA
#define BM 256
#define BN 64
#define BK 32
#define BKP 40            // padded A row (floats)
#define BNP 72            // padded B row (floats)
#define NCHUNKS (CIN / BK)

// dynamic smem layout (float offsets)
#define SM_A0 0
#define SM_A1 (BM * BKP)                       // 10240
#define SM_B0 (2 * BM * BKP)                   // 20480
#define SM_B1 (2 * BM * BKP + BK * BNP)        // 22784
#define SM_FLOATS (2 * BM * BKP + 2 * BK * BNP)  // 25088 -> 100352 bytes

// Device scratch (allocation-free per harness rules)
__device__ float g_pooled[BATCH * CIN];
__device__ float g_attn[BATCH * NEXP];
__device__ float g_wdyn[BATCH * COUT * CIN];   // 8 MB, stored tf32-rounded

__device__ __forceinline__ float tf32r(float f) {
    unsigned r;
    asm("cvt.rna.tf32.f32 %0, %1;" : "=r"(r) : "f"(f));
    return __uint_as_float(r);
}
__device__ __forceinline__ unsigned smem_u32(const void* p) {
    unsigned a;
    asm("{ .reg .u64 t; cvta.to.shared.u64 t, %1; cvt.u32.u64 %0, t; }" : "=r"(a) : "l"(p));
    return a;
}
__device__ __forceinline__ void cp_async16(unsigned dst, const void* src) {
    asm volatile("cp.async.cg.shared.global [%0], [%1], 16;" :: "r"(dst), "l"(src) : "memory");
}
#define CP_COMMIT() asm volatile("cp.async.commit_group;" ::: "memory")
#define CP_WAIT0()  asm volatile("cp.async.wait_group 0;" ::: "memory")

// ---------------------------------------------------------------------------
// Kernel 1: global average pool
// ---------------------------------------------------------------------------
__global__ void pool_kernel(const float* __restrict__ x) {
    const int bc = blockIdx.x;
    const float* __restrict__ p = x + (size_t)bc * HW;
    const int tid = threadIdx.x;

    float s = 0.0f;
    const float4* p4 = (const float4*)p;
    for (int i = tid; i < HW / 4; i += 256) {
        float4 v = p4[i];
        s += v.x + v.y + v.z + v.w;
    }
    for (int off = 16; off > 0; off >>= 1)
        s += __shfl_xor_sync(0xFFFFFFFFu, s, off);

    __shared__ float red[8];
    if ((tid & 31) == 0) red[tid >> 5] = s;
    __syncthreads();
    if (tid == 0) {
        float t = 0.0f;
        #pragma unroll
        for (int w = 0; w < 8; w++) t += red[w];
        g_pooled[bc] = t * (1.0f / (float)HW);
    }
}

// ---------------------------------------------------------------------------
// Kernel 2: MLP + softmax -> attn
// ---------------------------------------------------------------------------
__global__ void attn_kernel(const float* __restrict__ w1,
                            const float* __restrict__ b1,
                            const float* __restrict__ w2,
                            const float* __restrict__ b2) {
    const int b = blockIdx.x;
    const int t = threadIdx.x;

    __shared__ float sp[CIN];
    __shared__ float sh[CHID];
    __shared__ float sl[NEXP];

    for (int i = t; i < CIN; i += 64) sp[i] = g_pooled[b * CIN + i];
    __syncthreads();

    float acc = b1[t];
    const float* w1r = w1 + t * CIN;
    #pragma unroll 8
    for (int c = 0; c < CIN; c++) acc = fmaf(w1r[c], sp[c], acc);
    sh[t] = fmaxf(acc, 0.0f);
    __syncthreads();

    if (t < NEXP) {
        float l = b2[t];
        const float* w2r = w2 + t * CHID;
        #pragma unroll
        for (int j = 0; j < CHID; j++) l = fmaf(w2r[j], sh[j], l);
        sl[t] = l;
    }
    __syncthreads();

    if (t == 0) {
        float m = sl[0];
        #pragma unroll
        for (int e = 1; e < NEXP; e++) m = fmaxf(m, sl[e]);
        float sum = 0.0f;
        float ex[NEXP];
        #pragma unroll
        for (int e = 0; e < NEXP; e++) { ex[e] = __expf(sl[e] - m); sum += ex[e]; }
        float inv = 1.0f / sum;
        #pragma unroll
        for (int e = 0; e < NEXP; e++) g_attn[b * NEXP + e] = ex[e] * inv;
    }
}

// ---------------------------------------------------------------------------
// Kernel 3: w_dyn = attn . weights   (weights read once; all b per block)
// One block per co; smem caches weights[:, co, :]; output pre-rounded to tf32.
// ---------------------------------------------------------------------------
__global__ __launch_bounds__(256)
void wdyn_kernel(const float* __restrict__ weights) {
    const int co = blockIdx.x;
    const int ci = threadIdx.x;

    __shared__ float sw[NEXP][CIN];
    __shared__ float sa[BATCH][NEXP];

    #pragma unroll
    for (int e = 0; e < NEXP; e++)
        sw[e][ci] = weights[((size_t)e * COUT + co) * CIN + ci];
    if (ci < BATCH * NEXP)
        ((float*)sa)[ci] = g_attn[ci];
    __syncthreads();

    float w[NEXP];
    #pragma unroll
    for (int e = 0; e < NEXP; e++) w[e] = sw[e][ci];

    #pragma unroll 4
    for (int b = 0; b < BATCH; b++) {
        float s = 0.0f;
        #pragma unroll
        for (int e = 0; e < NEXP; e++) s = fmaf(sa[b][e], w[e], s);
        g_wdyn[((size_t)b * COUT + co) * CIN + ci] = tf32r(s);
    }
}

// ---------------------------------------------------------------------------
// Kernel 4: wmma tf32 batched GEMM
//   out[b] (256 x 3136) = w_dyn[b] (256 x 256) @ x[b] (256 x 3136)
//   CTA: 256 x 64.  A via cp.async (already tf32).  B reg-staged + cvt.
//   8 warps in 4x2; warp tile 64x32 = 4x2 m16n16k8 tf32 fragments.
// ---------------------------------------------------------------------------
__global__ __launch_bounds__(256, 2)
void gemm_wmma(const float* __restrict__ x, float* __restrict__ out) {
    extern __shared__ float sm[];
    const unsigned sbase = smem_u32(sm);

    const int tid = threadIdx.x;
    const int wid = tid >> 5;
    const int wm = wid >> 1;          // 0..3 -> m offset 64*wm
    const int wn = wid & 1;           // 0..1 -> n offset 32*wn

    const int n0 = blockIdx.x * BN;
    const int b  = blockIdx.y;

    const float* __restrict__ Ag = g_wdyn + (size_t)b * COUT * CIN;
    const float* __restrict__ Bg = x + (size_t)b * CIN * HW;

    // A cp.async mapping: 8 x 16B per thread
    const int am  = tid >> 3;         // 0..31 (+ i*32)
    const int ak4 = (tid & 7) * 4;    // 0..28
    // B mapping: 2 float4 per thread
    const int bk  = tid >> 4;         // 0..15 (+16)
    const int bn4 = (tid & 15) * 4;

    wmma::fragment<wmma::accumulator, 16, 16, 8, float> acc[4][2];
    #pragma unroll
    for (int i = 0; i < 4; i++)
        #pragma unroll
        for (int j = 0; j < 2; j++)
            wmma::fill_fragment(acc[i][j], 0.0f);

    float4 bReg[2];

    // ---- prologue: chunk 0 ----
    #pragma unroll
    for (int i = 0; i < 8; i++) {
        const int m = am + i * 32;
        cp_async16(sbase + (SM_A0 + m * BKP + ak4) * 4, Ag + (size_t)m * CIN + ak4);
    }
    CP_COMMIT();
    #pragma unroll
    for (int i = 0; i < 2; i++)
        bReg[i] = *(const float4*)(Bg + (size_t)(bk + i * 16) * HW + n0 + bn4);
    #pragma unroll
    for (int i = 0; i < 2; i++) {
        float4 v = make_float4(tf32r(bReg[i].x), tf32r(bReg[i].y),
                               tf32r(bReg[i].z), tf32r(bReg[i].w));
        *(float4*)(sm + SM_B0 + (bk + i * 16) * BNP + bn4) = v;
    }
    CP_WAIT0();
    __syncthreads();

    for (int c = 0; c < NCHUNKS; c++) {
        const int k1 = (c + 1) * BK;
        const unsigned an = (c & 1) ? SM_A0 : SM_A1;   // next buffers
        float* Bn = sm + ((c & 1) ? SM_B0 : SM_B1);

        if (c < NCHUNKS - 1) {
            #pragma unroll
            for (int i = 0; i < 8; i++) {
                const int m = am + i * 32;
                cp_async16(sbase + (an + m * BKP + ak4) * 4, Ag + (size_t)m * CIN + k1 + ak4);
            }
            CP_COMMIT();
            #pragma unroll
            for (int i = 0; i < 2; i++)
                bReg[i] = *(const float4*)(Bg + (size_t)(k1 + bk + i * 16) * HW + n0 + bn4);
        }

        const float* As = sm + (c & 1 ? SM_A1 : SM_A0);
        const float* Bs = sm + (c & 1 ? SM_B1 : SM_B0);

        #pragma unroll
        for (int ks = 0; ks < 4; ks++) {
            wmma::fragment<wmma::matrix_a, 16, 16, 8, wmma::precision::tf32, wmma::row_major> af[4];
            wmma::fragment<wmma::matrix_b, 16, 16, 8, wmma::precision::tf32, wmma::row_major> bf[2];
            #pragma unroll
            for (int i = 0; i < 4; i++)
                wmma::load_matrix_sync(af[i], As + (wm * 64 + i * 16) * BKP + ks * 8, BKP);
            #pragma unroll
            for (int j = 0; j < 2; j++)
                wmma::load_matrix_sync(bf[j], Bs + (ks * 8) * BNP + wn * 32 + j * 16, BNP);
            #pragma unroll
            for (int i = 0; i < 4; i++)
                #pragma unroll
                for (int j = 0; j < 2; j++)
                    wmma::mma_sync(acc[i][j], af[i], bf[j], acc[i][j]);
        }

        if (c < NCHUNKS - 1) {
            #pragma unroll
            for (int i = 0; i < 2; i++) {
                float4 v = make_float4(tf32r(bReg[i].x), tf32r(bReg[i].y),
                                       tf32r(bReg[i].z), tf32r(bReg[i].w));
                *(float4*)(Bn + (bk + i * 16) * BNP + bn4) = v;
            }
            CP_WAIT0();
        }
        __syncthreads();
    }

    // ---- epilogue ----
    float* __restrict__ C = out + (size_t)b * COUT * HW
                          + (size_t)(wm * 64) * HW + n0 + wn * 32;
    #pragma unroll
    for (int i = 0; i < 4; i++)
        #pragma unroll
        for (int j = 0; j < 2; j++)
            wmma::store_matrix_sync(C + (size_t)(i * 16) * HW + j * 16,
                                    acc[i][j], HW, wmma::mem_row_major);
}

// ---------------------------------------------------------------------------
// Launch
// ---------------------------------------------------------------------------
extern "C" void kernel_launch(void* const* d_in, const int* in_sizes, int n_in,
                              void* d_out, int out_size) {
    const float* x       = (const float*)d_in[0];
    const float* weights = (const float*)d_in[1];
    const float* w1      = (const float*)d_in[2];
    const float* b1      = (const float*)d_in[3];
    const float* w2      = (const float*)d_in[4];
    const float* b2      = (const float*)d_in[5];
    float* out = (float*)d_out;

    pool_kernel<<<BATCH * CIN, 256>>>(x);
    attn_kernel<<<BATCH, 64>>>(w1, b1, w2, b2);
    wdyn_kernel<<<COUT, 256>>>(weights);

    cudaFuncSetAttribute(gemm_wmma, cudaFuncAttributeMaxDynamicSharedMemorySize,
                         SM_FLOATS * (int)sizeof(float));
    dim3 grid(HW / BN, BATCH);     // 49 x 32
    gemm_wmma<<<grid, 256, SM_FLOATS * sizeof(float)>>>(x, out);
}

// round 6
// speedup vs baseline: 2.2495x; 2.2495x over previous
#include <cuda_runtime.h>
#include <cuda_bf16.h>

// Problem constants
#define BATCH 32
#define CIN   256
#define COUT  256
#define NEXP  8
#define CHID  64
#define HW    3136   // 56*56

// GEMM tiling
#define BM 128
#define BN 112            // 3136 = 28 * 112
#define BK 32
#define BNP 120           // padded B row (floats) -> conflict-free B frag LDS
#define NCHUNKS (CIN / BK)

// dynamic smem layout (float offsets)
#define SA0 0
#define SA1 4096          // A chunk = 8 mtiles * 4 ks * 32 lanes * 4 = 4096 floats
#define SB0 8192
#define SB1 (8192 + BK * BNP)          // 12032
#define SM_FLOATS (8192 + 2 * BK * BNP)  // 15872 floats = 63488 bytes

// Device scratch (allocation-free per harness rules)
__device__ float g_pooled[BATCH * CIN];
__device__ float g_attn[BATCH * NEXP];
// A in m16n8k8 fragment layout: [b][mtile 16][ksgroup 32][lane 32][reg 4]
__device__ float g_wdyn[BATCH * 16 * 32 * 32 * 4];   // 8 MB, tf32(rna)-rounded

__device__ __forceinline__ float tf32r(float f) {
    unsigned r;
    asm("cvt.rna.tf32.f32 %0, %1;" : "=r"(r) : "f"(f));
    return __uint_as_float(r);
}
__device__ __forceinline__ unsigned smem_u32(const void* p) {
    unsigned a;
    asm("{ .reg .u64 t; cvta.to.shared.u64 t, %1; cvt.u32.u64 %0, t; }" : "=r"(a) : "l"(p));
    return a;
}
__device__ __forceinline__ void cp_async16(unsigned dst, const void* src) {
    asm volatile("cp.async.cg.shared.global [%0], [%1], 16;" :: "r"(dst), "l"(src) : "memory");
}
#define CP_COMMIT() asm volatile("cp.async.commit_group;" ::: "memory")
#define CP_WAIT0()  asm volatile("cp.async.wait_group 0;" ::: "memory")

__device__ __forceinline__ void mma8(float4& d, const float4& a, float b0, float b1) {
    asm volatile(
        "mma.sync.aligned.m16n8k8.row.col.f32.tf32.tf32.f32 "
        "{%0,%1,%2,%3}, {%4,%5,%6,%7}, {%8,%9}, {%0,%1,%2,%3};"
        : "+f"(d.x), "+f"(d.y), "+f"(d.z), "+f"(d.w)
        : "r"(__float_as_uint(a.x)), "r"(__float_as_uint(a.y)),
          "r"(__float_as_uint(a.z)), "r"(__float_as_uint(a.w)),
          "r"(__float_as_uint(b0)), "r"(__float_as_uint(b1)));
}

// ---------------------------------------------------------------------------
// Kernel 1: global average pool
// ---------------------------------------------------------------------------
__global__ void pool_kernel(const float* __restrict__ x) {
    const int bc = blockIdx.x;
    const float* __restrict__ p = x + (size_t)bc * HW;
    const int tid = threadIdx.x;

    float s = 0.0f;
    const float4* p4 = (const float4*)p;
    for (int i = tid; i < HW / 4; i += 256) {
        float4 v = p4[i];
        s += v.x + v.y + v.z + v.w;
    }
    for (int off = 16; off > 0; off >>= 1)
        s += __shfl_xor_sync(0xFFFFFFFFu, s, off);

    __shared__ float red[8];
    if ((tid & 31) == 0) red[tid >> 5] = s;
    __syncthreads();
    if (tid == 0) {
        float t = 0.0f;
        #pragma unroll
        for (int w = 0; w < 8; w++) t += red[w];
        g_pooled[bc] = t * (1.0f / (float)HW);
    }
}

// ---------------------------------------------------------------------------
// Kernel 2: MLP + softmax -> attn
// ---------------------------------------------------------------------------
__global__ void attn_kernel(const float* __restrict__ w1,
                            const float* __restrict__ b1,
                            const float* __restrict__ w2,
                            const float* __restrict__ b2) {
    const int b = blockIdx.x;
    const int t = threadIdx.x;

    __shared__ float sp[CIN];
    __shared__ float sh[CHID];
    __shared__ float sl[NEXP];

    for (int i = t; i < CIN; i += 64) sp[i] = g_pooled[b * CIN + i];
    __syncthreads();

    float acc = b1[t];
    const float* w1r = w1 + t * CIN;
    #pragma unroll 8
    for (int c = 0; c < CIN; c++) acc = fmaf(w1r[c], sp[c], acc);
    sh[t] = fmaxf(acc, 0.0f);
    __syncthreads();

    if (t < NEXP) {
        float l = b2[t];
        const float* w2r = w2 + t * CHID;
        #pragma unroll
        for (int j = 0; j < CHID; j++) l = fmaf(w2r[j], sh[j], l);
        sl[t] = l;
    }
    __syncthreads();

    if (t == 0) {
        float m = sl[0];
        #pragma unroll
        for (int e = 1; e < NEXP; e++) m = fmaxf(m, sl[e]);
        float sum = 0.0f;
        float ex[NEXP];
        #pragma unroll
        for (int e = 0; e < NEXP; e++) { ex[e] = __expf(sl[e] - m); sum += ex[e]; }
        float inv = 1.0f / sum;
        #pragma unroll
        for (int e = 0; e < NEXP; e++) g_attn[b * NEXP + e] = ex[e] * inv;
    }
}

// ---------------------------------------------------------------------------
// Kernel 3: w_dyn = attn . weights, written in m16n8k8 A-fragment layout,
// tf32(rna)-rounded.  One block per co; weights read exactly once.
// Element (co, ci): mt=co>>4, r=co&15, ksg=ci>>3, cl=ci&7,
//   lane=(r&7)*4+(cl&3), reg=((r>>3)&1)+2*((cl>>2)&1)
// ---------------------------------------------------------------------------
__global__ __launch_bounds__(256)
void wdyn_kernel(const float* __restrict__ weights) {
    const int co = blockIdx.x;
    const int ci = threadIdx.x;

    __shared__ float sw[NEXP][CIN];
    __shared__ float sa[BATCH][NEXP];

    #pragma unroll
    for (int e = 0; e < NEXP; e++)
        sw[e][ci] = weights[((size_t)e * COUT + co) * CIN + ci];
    if (ci < BATCH * NEXP)
        ((float*)sa)[ci] = g_attn[ci];
    __syncthreads();

    float w[NEXP];
    #pragma unroll
    for (int e = 0; e < NEXP; e++) w[e] = sw[e][ci];

    const int mt  = co >> 4;
    const int r   = co & 15;
    const int ksg = ci >> 3;
    const int cl  = ci & 7;
    const int lane = (r & 7) * 4 + (cl & 3);
    const int reg  = ((r >> 3) & 1) + 2 * ((cl >> 2) & 1);
    const size_t base = ((size_t)(mt * 32 + ksg) * 32 + lane) * 4 + reg;

    #pragma unroll 4
    for (int b = 0; b < BATCH; b++) {
        float s = 0.0f;
        #pragma unroll
        for (int e = 0; e < NEXP; e++) s = fmaf(sa[b][e], w[e], s);
        g_wdyn[(size_t)b * (16 * 32 * 32 * 4) + base] = tf32r(s);
    }
}

// ---------------------------------------------------------------------------
// Kernel 4: hand-rolled m16n8k8 tf32 batched GEMM
//   out[b] (256 x 3136) = w_dyn[b] @ x[b]
//   CTA 128 x 112; 8 warps (4m x 2n); warp tile 32 x 56 (2 x 7 mma tiles).
//   A: fragment-layout cp.async -> one LDS.128 per fragment.
//   B: reg-staged LDG + cvt.rna + STS (row pad 120 -> conflict-free frags).
// ---------------------------------------------------------------------------
__global__ __launch_bounds__(256, 2)
void gemm_mma(const float* __restrict__ x, float* __restrict__ out) {
    extern __shared__ float sm[];
    const unsigned sbase = smem_u32(sm);

    const int tid  = threadIdx.x;
    const int wid  = tid >> 5;
    const int lane = tid & 31;
    const int wm = wid >> 1;          // 0..3  (m offset 32*wm)
    const int wn = wid & 1;           // 0..1  (n offset 56*wn)

    const int n0 = blockIdx.x * BN;
    const int mb = blockIdx.y;        // 0..1
    const int b  = blockIdx.z;

    // A fragment source base for this CTA: mtiles mb*8 .. mb*8+7
    const float* __restrict__ Afrag = g_wdyn + (size_t)(b * 16 + mb * 8) * (32 * 32 * 4);
    const float* __restrict__ Bg = x + (size_t)b * CIN * HW;

    // B global->reg mapping: 896 float4 units; unit u: krow=u/28, c4=u%28
    // thread handles u = tid + i*256 (i<3) and u = 768+tid (tid<128)
    const int kr0 = tid / 28,  nc0 = (tid % 28) * 4;
    const int kr1 = (tid + 256) / 28, nc1 = ((tid + 256) % 28) * 4;
    const int kr2 = (tid + 512) / 28, nc2 = ((tid + 512) % 28) * 4;
    const int kr3 = (tid + 768) / 28, nc3 = ((tid + 768) % 28) * 4;

    float4 acc[2][7];
    #pragma unroll
    for (int i = 0; i < 2; i++)
        #pragma unroll
        for (int j = 0; j < 7; j++)
            acc[i][j] = make_float4(0.f, 0.f, 0.f, 0.f);

    float4 bReg[4];

    // ---- A cp.async helper mapping: 1024 16B units per chunk ----
    // unit u: mt_l = u>>7, ks = (u>>5)&3, l = u&31
    // src float idx = ((mt_l*32 + c*4 + ks)*32 + l) * 4
    // dst float idx = u*4
    // thread copies u = tid*4 + i, i<4  (contiguous 64B per thread)

    // ---- prologue: chunk 0 ----
    {
        #pragma unroll
        for (int i = 0; i < 4; i++) {
            const int u = tid * 4 + i;
            const int mt_l = u >> 7, ks = (u >> 5) & 3, l = u & 31;
            cp_async16(sbase + (SA0 + u * 4) * 4,
                       Afrag + ((size_t)(mt_l * 32 + ks) * 32 + l) * 4);
        }
        CP_COMMIT();
        bReg[0] = *(const float4*)(Bg + (size_t)kr0 * HW + n0 + nc0);
        bReg[1] = *(const float4*)(Bg + (size_t)kr1 * HW + n0 + nc1);
        bReg[2] = *(const float4*)(Bg + (size_t)kr2 * HW + n0 + nc2);
        if (tid < 128) bReg[3] = *(const float4*)(Bg + (size_t)kr3 * HW + n0 + nc3);

        float* Bs = sm + SB0;
        #pragma unroll
        for (int i = 0; i < 3; i++) {
            const int kr = (i == 0) ? kr0 : (i == 1) ? kr1 : kr2;
            const int nc = (i == 0) ? nc0 : (i == 1) ? nc1 : nc2;
            float4 v = make_float4(tf32r(bReg[i].x), tf32r(bReg[i].y),
                                   tf32r(bReg[i].z), tf32r(bReg[i].w));
            *(float4*)(Bs + kr * BNP + nc) = v;
        }
        if (tid < 128) {
            float4 v = make_float4(tf32r(bReg[3].x), tf32r(bReg[3].y),
                                   tf32r(bReg[3].z), tf32r(bReg[3].w));
            *(float4*)(Bs + kr3 * BNP + nc3) = v;
        }
        CP_WAIT0();
        __syncthreads();
    }

    for (int c = 0; c < NCHUNKS; c++) {
        const float* As = sm + ((c & 1) ? SA1 : SA0);
        const float* Bs = sm + ((c & 1) ? SB1 : SB0);

        if (c < NCHUNKS - 1) {
            const unsigned an = (c & 1) ? SA0 : SA1;
            const int k1 = (c + 1) * BK;
            #pragma unroll
            for (int i = 0; i < 4; i++) {
                const int u = tid * 4 + i;
                const int mt_l = u >> 7, ks = (u >> 5) & 3, l = u & 31;
                cp_async16(sbase + (an + u * 4) * 4,
                           Afrag + ((size_t)(mt_l * 32 + (c + 1) * 4 + ks) * 32 + l) * 4);
            }
            CP_COMMIT();
            bReg[0] = *(const float4*)(Bg + (size_t)(k1 + kr0) * HW + n0 + nc0);
            bReg[1] = *(const float4*)(Bg + (size_t)(k1 + kr1) * HW + n0 + nc1);
            bReg[2] = *(const float4*)(Bg + (size_t)(k1 + kr2) * HW + n0 + nc2);
            if (tid < 128) bReg[3] = *(const float4*)(Bg + (size_t)(k1 + kr3) * HW + n0 + nc3);
        }

        // ---- MMA over current chunk ----
        const int kr = lane & 3;            // k row within 8-group
        const int gc = lane >> 2;           // n col within 8-tile
        #pragma unroll
        for (int ks = 0; ks < 4; ks++) {
            float4 a0 = *(const float4*)(As + ((size_t)((wm * 2 + 0) * 4 + ks) * 32 + lane) * 4);
            float4 a1 = *(const float4*)(As + ((size_t)((wm * 2 + 1) * 4 + ks) * 32 + lane) * 4);
            const float* brow0 = Bs + (ks * 8 + kr) * BNP + wn * 56 + gc;
            const float* brow1 = brow0 + 4 * BNP;
            #pragma unroll
            for (int nt = 0; nt < 7; nt++) {
                const float b0 = brow0[nt * 8];
                const float b1 = brow1[nt * 8];
                mma8(acc[0][nt], a0, b0, b1);
                mma8(acc[1][nt], a1, b0, b1);
            }
        }

        if (c < NCHUNKS - 1) {
            float* Bn = sm + ((c & 1) ? SB0 : SB1);
            #pragma unroll
            for (int i = 0; i < 3; i++) {
                const int kri = (i == 0) ? kr0 : (i == 1) ? kr1 : kr2;
                const int nci = (i == 0) ? nc0 : (i == 1) ? nc1 : nc2;
                float4 v = make_float4(tf32r(bReg[i].x), tf32r(bReg[i].y),
                                       tf32r(bReg[i].z), tf32r(bReg[i].w));
                *(float4*)(Bn + kri * BNP + nci) = v;
            }
            if (tid < 128) {
                float4 v = make_float4(tf32r(bReg[3].x), tf32r(bReg[3].y),
                                       tf32r(bReg[3].z), tf32r(bReg[3].w));
                *(float4*)(Bn + kr3 * BNP + nc3) = v;
            }
            CP_WAIT0();
        }
        __syncthreads();
    }

    // ---- epilogue: direct STG.64 per accumulator half ----
    const int r  = lane >> 2;
    const int t2 = (lane & 3) * 2;
    float* __restrict__ C = out + (size_t)b * COUT * HW
                          + (size_t)(mb * BM + wm * 32) * HW + n0 + wn * 56;
    #pragma unroll
    for (int it = 0; it < 2; it++) {
        #pragma unroll
        for (int nt = 0; nt < 7; nt++) {
            float* p0 = C + (size_t)(it * 16 + r) * HW + nt * 8 + t2;
            float* p1 = p0 + 8 * HW;
            *(float2*)p0 = make_float2(acc[it][nt].x, acc[it][nt].y);
            *(float2*)p1 = make_float2(acc[it][nt].z, acc[it][nt].w);
        }
    }
}

// ---------------------------------------------------------------------------
// Launch
// ---------------------------------------------------------------------------
extern "C" void kernel_launch(void* const* d_in, const int* in_sizes, int n_in,
                              void* d_out, int out_size) {
    const float* x       = (const float*)d_in[0];
    const float* weights = (const float*)d_in[1];
    const float* w1      = (const float*)d_in[2];
    const float* b1      = (const float*)d_in[3];
    const float* w2      = (const float*)d_in[4];
    const float* b2      = (const float*)d_in[5];
    float* out = (float*)d_out;

    pool_kernel<<<BATCH * CIN, 256>>>(x);
    attn_kernel<<<BATCH, 64>>>(w1, b1, w2, b2);
    wdyn_kernel<<<COUT, 256>>>(weights);

    cudaFuncSetAttribute(gemm_mma, cudaFuncAttributeMaxDynamicSharedMemorySize,
                         SM_FLOATS * (int)sizeof(float));
    dim3 grid(HW / BN, COUT / BM, BATCH);   // 28 x 2 x 32
    gemm_mma<<<grid, 256, SM_FLOATS * sizeof(float)>>>(x, out);
}